// round 1
// baseline (speedup 1.0000x reference)
#include <cuda_runtime.h>
#include <cstdint>

// ---------------------------------------------------------------------------
// AttentionLayer (linear attention) — fused fp32 baseline with f32x2 FMA.
//
// Shapes (fixed by the problem):
//   B=4, N=80, H=24, W=24  -> n = 2304 spatial tokens
//   S=77, C=256 (hidden+guid), hidden=128, NHEADS=8, Dh=16
//
// Kernel A (per n): K = elu([x|g] @ Wk + bk)+1, V = x @ Wv + bv
//                   KV[h][d][dv] = sum_s K*V ;  Ksum[c] = sum_s K
// Kernel B (per n): Q = elu(qin @ Wq + bq)+1
//                   Z[l][h] = 1/(Q . Ksum + eps)
//                   out[c] = mean_l Z * (Q . KV)      (S and 1/S cancel)
// ---------------------------------------------------------------------------

#define NTOK   2304
#define SEQ    77
#define NQ     80
#define CIN    256
#define HID    128
#define NHEADS 8
#define DH     16

// scratch (static device arrays: allocation-free per harness rules)
__device__ float g_KV[NTOK * NHEADS * DH * DH];   // [n][h][d][dv]  (18.9 MB)
__device__ float g_Ksum[NTOK * HID];              // [n][c]

// ---- packed f32x2 helpers -------------------------------------------------
__device__ __forceinline__ unsigned long long pk2(float x) {
    unsigned long long r;
    asm("mov.b64 %0, {%1, %1};" : "=l"(r) : "r"(__float_as_uint(x)));
    return r;
}
__device__ __forceinline__ unsigned long long fma2(unsigned long long a,
                                                   unsigned long long b,
                                                   unsigned long long c) {
    unsigned long long d;
    asm("fma.rn.f32x2 %0, %1, %2, %3;" : "=l"(d) : "l"(a), "l"(b), "l"(c));
    return d;
}
__device__ __forceinline__ void up2(unsigned long long v, float& lo, float& hi) {
    unsigned l, h;
    asm("mov.b64 {%0, %1}, %2;" : "=r"(l), "=r"(h) : "l"(v));
    lo = __uint_as_float(l);
    hi = __uint_as_float(h);
}
__device__ __forceinline__ float featmap(float x) {      // elu(x)+1
    return x > 0.f ? x + 1.f : __expf(x);
}

// ---------------------------------------------------------------------------
// 80x128 GEMM: Cs[80][128] = As[80][KD] @ Wg[KD][128] + bias, opt. elu+1.
// As: smem, row stride 260 floats (pad kills bank conflicts).
// Wg: global weights, staged through 32x128 smem tile ws.
// 256 threads: tx=tid&15 -> 8 cols {tx*4..+3, 64+tx*4..+3}; ty=tid>>4 -> rows ty*5..+4.
// Accumulators are packed f32x2 pairs -> 20 FFMA2 per (thread, j).
// ---------------------------------------------------------------------------
template <int KD, bool ACT>
__device__ __forceinline__ void gemm80(const float* __restrict__ As,
                                       const float* __restrict__ Wg,
                                       const float* __restrict__ bias,
                                       float* ws, float* Cs, int tid) {
    const int tx = tid & 15, ty = tid >> 4;
    const int r0 = ty * 5;
    unsigned long long acc[5][4];
#pragma unroll
    for (int i = 0; i < 5; i++)
#pragma unroll
        for (int p = 0; p < 4; p++) acc[i][p] = 0ULL;

    for (int kt = 0; kt < KD; kt += 32) {
        // stage 32x128 weight tile
        const float4* src = (const float4*)(Wg + kt * HID);
        float4* dst = (float4*)ws;
#pragma unroll
        for (int u = 0; u < 4; u++) dst[tid + 256 * u] = src[tid + 256 * u];
        __syncthreads();

#pragma unroll 8
        for (int jj = 0; jj < 32; jj++) {
            const unsigned long long* wp0 =
                (const unsigned long long*)(ws + jj * HID + tx * 4);
            const unsigned long long* wp1 =
                (const unsigned long long*)(ws + jj * HID + 64 + tx * 4);
            unsigned long long b0 = wp0[0], b1 = wp0[1];
            unsigned long long b2 = wp1[0], b3 = wp1[1];
#pragma unroll
            for (int i = 0; i < 5; i++) {
                unsigned long long ad = pk2(As[(r0 + i) * 260 + kt + jj]);
                acc[i][0] = fma2(ad, b0, acc[i][0]);
                acc[i][1] = fma2(ad, b1, acc[i][1]);
                acc[i][2] = fma2(ad, b2, acc[i][2]);
                acc[i][3] = fma2(ad, b3, acc[i][3]);
            }
        }
        __syncthreads();
    }

    float4 blo = *(const float4*)(bias + tx * 4);
    float4 bhi = *(const float4*)(bias + 64 + tx * 4);
#pragma unroll
    for (int i = 0; i < 5; i++) {
        float4 o0, o1;
        up2(acc[i][0], o0.x, o0.y);
        up2(acc[i][1], o0.z, o0.w);
        up2(acc[i][2], o1.x, o1.y);
        up2(acc[i][3], o1.z, o1.w);
        o0.x += blo.x; o0.y += blo.y; o0.z += blo.z; o0.w += blo.w;
        o1.x += bhi.x; o1.y += bhi.y; o1.z += bhi.z; o1.w += bhi.w;
        if (ACT) {
            o0.x = featmap(o0.x); o0.y = featmap(o0.y);
            o0.z = featmap(o0.z); o0.w = featmap(o0.w);
            o1.x = featmap(o1.x); o1.y = featmap(o1.y);
            o1.z = featmap(o1.z); o1.w = featmap(o1.w);
        }
        *(float4*)(Cs + (r0 + i) * HID + tx * 4) = o0;
        *(float4*)(Cs + (r0 + i) * HID + 64 + tx * 4) = o1;
    }
}

// ---------------------------------------------------------------------------
// Kernel A: K/V GEMMs + KV & Ksum reduction.   smem = 181,504 B
// ---------------------------------------------------------------------------
__global__ void __launch_bounds__(256, 1)
kA(const float* __restrict__ x, const float* __restrict__ gdc,
   const float* __restrict__ Wk, const float* __restrict__ bk,
   const float* __restrict__ Wv, const float* __restrict__ bv) {
    extern __shared__ float sm[];
    float* xg = sm;                 // 80*260 = 20800 (rows 77..79 zeroed)
    float* ws = xg + 20800;         // 4096
    float* kk = ws + 4096;          // 80*128 = 10240
    float* vv = kk + 10240;         // 10240
    const int n = blockIdx.x, tid = threadIdx.x;

    // fill [x | guidance] into xg (vectorized, padded row stride)
    const float4* xs = (const float4*)(x + (size_t)n * SEQ * HID);
    const float4* gs = (const float4*)(gdc + (size_t)n * SEQ * HID);
    for (int idx = tid; idx < SEQ * 32; idx += 256) {
        int s = idx >> 5, j4 = idx & 31;
        ((float4*)(xg + s * 260))[j4] = xs[idx];
        ((float4*)(xg + s * 260 + HID))[j4] = gs[idx];
    }
    for (int idx = tid; idx < 3 * 260; idx += 256) xg[SEQ * 260 + idx] = 0.f;

    gemm80<CIN, true>(xg, Wk, bk, ws, kk, tid);    // K = elu(.)+1
    gemm80<HID, false>(xg, Wv, bv, ws, vv, tid);   // V
    __syncthreads();

    // Ksum
    if (tid < HID) {
        float s = 0.f;
        for (int t = 0; t < SEQ; t++) s += kk[t * HID + tid];
        g_Ksum[(size_t)n * HID + tid] = s;
    }
    // KV: each thread owns 8 consecutive dv of one (h,d)
    {
        const int h = tid >> 5, lane = tid & 31;
        const int d = lane >> 1, dv0 = (lane & 1) * 8;
        float a[8] = {0, 0, 0, 0, 0, 0, 0, 0};
        for (int t = 0; t < SEQ; t++) {
            float kval = kk[t * HID + h * DH + d];
            float4 va = *(const float4*)(vv + t * HID + h * DH + dv0);
            float4 vb = *(const float4*)(vv + t * HID + h * DH + dv0 + 4);
            a[0] = fmaf(kval, va.x, a[0]); a[1] = fmaf(kval, va.y, a[1]);
            a[2] = fmaf(kval, va.z, a[2]); a[3] = fmaf(kval, va.w, a[3]);
            a[4] = fmaf(kval, vb.x, a[4]); a[5] = fmaf(kval, vb.y, a[5]);
            a[6] = fmaf(kval, vb.z, a[6]); a[7] = fmaf(kval, vb.w, a[7]);
        }
        float* dst = g_KV + (size_t)n * 2048 + tid * 8;
        *(float4*)dst = make_float4(a[0], a[1], a[2], a[3]);
        *(float4*)(dst + 4) = make_float4(a[4], a[5], a[6], a[7]);
    }
}

// ---------------------------------------------------------------------------
// Kernel B: Q GEMM + Z + output.   smem = 152,832 B
// ---------------------------------------------------------------------------
__global__ void __launch_bounds__(256, 1)
kB(const float* __restrict__ query, const float* __restrict__ Wq,
   const float* __restrict__ bq, float* __restrict__ out) {
    extern __shared__ float sm[];
    float* qs  = sm;                // 20800
    float* ws  = qs + 20800;        // 4096
    float* qq  = ws + 4096;         // 10240
    float* kvs = qq + 10240;        // 2048
    float* ks  = kvs + 2048;        // 128
    float* Zs  = ks + 128;          // 640
    float* red = Zs + 640;          // 256
    const int n = blockIdx.x, tid = threadIdx.x;

    const int b = n / 576, rem = n - b * 576;        // rem = h*24 + w
    const float* qbase = query + ((size_t)b * NQ * 576 + rem) * CIN;
    for (int idx = tid; idx < NQ * 64; idx += 256) {
        int l = idx >> 6, j4 = idx & 63;
        ((float4*)(qs + l * 260))[j4] =
            ((const float4*)(qbase + (size_t)l * 576 * CIN))[j4];
    }
    {
        const float4* kvsrc = (const float4*)(g_KV + (size_t)n * 2048);
        for (int u = tid; u < 512; u += 256) ((float4*)kvs)[u] = kvsrc[u];
        if (tid < 32)
            ((float4*)ks)[tid] = ((const float4*)(g_Ksum + (size_t)n * HID))[tid];
    }

    gemm80<CIN, true>(qs, Wq, bq, ws, qq, tid);      // Q = elu(.)+1
    __syncthreads();

    // Z[l][h]
    for (int e = tid; e < NQ * NHEADS; e += 256) {
        int l = e >> 3, h = e & 7;
        float dot = 0.f;
#pragma unroll
        for (int d = 0; d < DH; d++)
            dot = fmaf(qq[l * HID + h * DH + d], ks[h * DH + d], dot);
        Zs[e] = 1.0f / (dot + 1e-6f);
    }
    __syncthreads();

    // out[c] = mean_l Z[l,h] * sum_d Q[l,h,d]*KV[h,d,dv]
    const int c = tid & 127, g = tid >> 7;
    const int h = c >> 4, dv = c & 15;
    float kvc[DH];
#pragma unroll
    for (int d = 0; d < DH; d++) kvc[d] = kvs[h * 256 + d * DH + dv];
    float acc = 0.f;
    for (int l = g * 40; l < g * 40 + 40; l++) {
        const float4* qp = (const float4*)(qq + l * HID + h * DH);
        float4 q0 = qp[0], q1 = qp[1], q2 = qp[2], q3 = qp[3];
        float p0 = fmaf(q0.x, kvc[0], fmaf(q0.y, kvc[1], fmaf(q0.z, kvc[2], q0.w * kvc[3])));
        float p1 = fmaf(q1.x, kvc[4], fmaf(q1.y, kvc[5], fmaf(q1.z, kvc[6], q1.w * kvc[7])));
        float p2 = fmaf(q2.x, kvc[8], fmaf(q2.y, kvc[9], fmaf(q2.z, kvc[10], q2.w * kvc[11])));
        float p3 = fmaf(q3.x, kvc[12], fmaf(q3.y, kvc[13], fmaf(q3.z, kvc[14], q3.w * kvc[15])));
        acc = fmaf(Zs[l * 8 + h], (p0 + p1) + (p2 + p3), acc);
    }
    red[tid] = acc;
    __syncthreads();
    if (tid < HID)
        out[(size_t)n * HID + tid] = (red[tid] + red[tid + HID]) * (1.0f / 80.0f);
}

// ---------------------------------------------------------------------------
static const int A_SMEM = (20800 + 4096 + 10240 + 10240) * 4;   // 181,504 B
static const int B_SMEM = (20800 + 4096 + 10240 + 2048 + 128 + 640 + 256) * 4; // 152,832 B

extern "C" void kernel_launch(void* const* d_in, const int* in_sizes, int n_in,
                              void* d_out, int out_size) {
    const float* query = (const float*)d_in[0];
    const float* x     = (const float*)d_in[1];
    const float* gdc   = (const float*)d_in[2];
    const float* Wq    = (const float*)d_in[3];
    const float* bq    = (const float*)d_in[4];
    const float* Wk    = (const float*)d_in[5];
    const float* bk    = (const float*)d_in[6];
    const float* Wv    = (const float*)d_in[7];
    const float* bv    = (const float*)d_in[8];
    float* out = (float*)d_out;

    cudaFuncSetAttribute(kA, cudaFuncAttributeMaxDynamicSharedMemorySize, A_SMEM);
    cudaFuncSetAttribute(kB, cudaFuncAttributeMaxDynamicSharedMemorySize, B_SMEM);

    kA<<<NTOK, 256, A_SMEM>>>(x, gdc, Wk, bk, Wv, bv);
    kB<<<NTOK, 256, B_SMEM>>>(query, Wq, bq, out);
}

// round 4
// speedup vs baseline: 1.4208x; 1.4208x over previous
#include <cuda_runtime.h>
#include <cuda_bf16.h>
#include <cstdint>

// ---------------------------------------------------------------------------
// Linear attention via mma.sync bf16-split (baseline PTX: works on .target
// sm_103 — tcgen05/'a'-features are rejected by this toolchain's ptxas stage).
//   n=2304, S=77, N=80, C=256, hidden=128, 8 heads x 16
// kA: K = elu([x|g]@Wk+bk)+1 ; V = x@Wv+bv ; KV[h][d][dv], Ksum[c]
// kB: Q = elu(qin@Wq+bq)+1 ; Z = 1/(Q.Ksum+eps) ; out = mean_l Z*(Q.KV)
// Split: A=Ahi+Alo, W=Whi+Wlo (bf16); D += Ahi*Whi + Ahi*Wlo + Alo*Whi.
// ---------------------------------------------------------------------------

#define NTOK 2304
#define SEQ  77
#define NQ   80
#define HID  128

// global scratch (allocation-free per harness rules)
__device__ float g_KV[NTOK * 2048];
__device__ float g_Ksum[NTOK * HID];
// fragment-ordered weight images: [kstep][gn][lane] -> uint4(hi01,hi89,lo01,lo89)
__device__ uint4 g_wk[16 * 16 * 32];   // K=256
__device__ uint4 g_wq[16 * 16 * 32];   // K=256
__device__ uint4 g_wv[8 * 16 * 32];    // K=128

// ---- helpers --------------------------------------------------------------
__device__ __forceinline__ uint32_t smem_u32(const void* p) {
    uint32_t a;
    asm("{ .reg .u64 t; cvta.to.shared.u64 t, %1; cvt.u32.u64 %0, t; }"
        : "=r"(a) : "l"(p));
    return a;
}
__device__ __forceinline__ void mma16816(float* d, const uint32_t* a,
                                         uint32_t b0, uint32_t b1) {
    asm volatile(
        "mma.sync.aligned.m16n8k16.row.col.f32.bf16.bf16.f32 "
        "{%0,%1,%2,%3}, {%4,%5,%6,%7}, {%8,%9}, {%0,%1,%2,%3};"
        : "+f"(d[0]), "+f"(d[1]), "+f"(d[2]), "+f"(d[3])
        : "r"(a[0]), "r"(a[1]), "r"(a[2]), "r"(a[3]), "r"(b0), "r"(b1));
}
__device__ __forceinline__ void ldsm4(uint32_t* r, uint32_t addr) {
    asm volatile("ldmatrix.sync.aligned.m8n8.x4.shared.b16 {%0,%1,%2,%3}, [%4];"
                 : "=r"(r[0]), "=r"(r[1]), "=r"(r[2]), "=r"(r[3]) : "r"(addr));
}
__device__ __forceinline__ uint32_t pack_hi(float v0, float v1) {
    uint32_t w;
    asm("cvt.rn.bf16x2.f32 %0, %1, %2;" : "=r"(w) : "f"(v1), "f"(v0));
    return w;  // lower half = v0
}
__device__ __forceinline__ float featmap(float x) {
    return x > 0.f ? x + 1.f : __expf(x);
}

// fp32 rows -> bf16 hi/lo into smem A-tiles, row stride 264 elements (528 B)
template <int PAIRS>  // fp32 pairs per row (64 -> 128 cols, 128 -> 256 cols)
__device__ __forceinline__ void conv_tile(const float* __restrict__ src,
                                          long rstride, int rows, char* hi_base,
                                          char* lo_base, int colbase, int tid,
                                          int nthr) {
    for (int idx = tid; idx < rows * PAIRS; idx += nthr) {
        int r = idx / PAIRS, j = idx % PAIRS;
        float2 v = *(const float2*)(src + (long)r * rstride + 2 * j);
        uint32_t hw = pack_hi(v.x, v.y);
        float r0 = v.x - __uint_as_float(hw << 16);
        float r1 = v.y - __uint_as_float(hw & 0xffff0000u);
        uint32_t lw = pack_hi(r0, r1);
        int off = (r * 264 + colbase + 2 * j) * 2;
        *(uint32_t*)(hi_base + off) = hw;
        *(uint32_t*)(lo_base + off) = lw;
    }
}

// ---------------------------------------------------------------------------
// warp-tile GEMM: C[80][128] = A[80][K] @ W[K][128] (+bias, opt elu+1)
// 10 warps: wm=wid>>1 (5 M-tiles of 16), wn=wid&1 (2 N-halves of 64).
// A: smem hi/lo bf16, stride 264. W: fragment-ordered global image.
// dst: smem fp32, row stride 132.
// ---------------------------------------------------------------------------
template <int KSTEPS, bool ACT>
__device__ __forceinline__ void gemm_mma(uint32_t ahi, uint32_t alo,
                                         const uint4* __restrict__ wimg,
                                         const float* __restrict__ bias,
                                         float* dst, int wid, int lane) {
    const int wm = wid >> 1, wn = wid & 1;
    const int mbase = wm * 16;
    float acc[8][4];
#pragma unroll
    for (int i = 0; i < 8; i++)
#pragma unroll
        for (int p = 0; p < 4; p++) acc[i][p] = 0.f;

    const int row_a = mbase + (lane & 7) + ((lane >> 3) & 1) * 8;
    const int kbyte = (lane >> 4) * 16;
    const uint32_t a_hi = ahi + row_a * 528 + kbyte;
    const uint32_t a_lo = alo + row_a * 528 + kbyte;

    uint4 wb[8];
#pragma unroll
    for (int nf = 0; nf < 8; nf++)
        wb[nf] = wimg[(0 * 16 + wn * 8 + nf) * 32 + lane];

    for (int ks = 0; ks < KSTEPS; ks++) {
        uint4 wn8[8];
        if (ks + 1 < KSTEPS) {
#pragma unroll
            for (int nf = 0; nf < 8; nf++)
                wn8[nf] = wimg[((ks + 1) * 16 + wn * 8 + nf) * 32 + lane];
        }
        uint32_t ah[4], al[4];
        ldsm4(ah, a_hi + ks * 32);
        ldsm4(al, a_lo + ks * 32);
#pragma unroll
        for (int nf = 0; nf < 8; nf++) {
            mma16816(acc[nf], ah, wb[nf].x, wb[nf].y);   // hi*Whi
            mma16816(acc[nf], ah, wb[nf].z, wb[nf].w);   // hi*Wlo
            mma16816(acc[nf], al, wb[nf].x, wb[nf].y);   // lo*Whi
        }
        if (ks + 1 < KSTEPS) {
#pragma unroll
            for (int nf = 0; nf < 8; nf++) wb[nf] = wn8[nf];
        }
    }
    // epilogue: bias + optional elu+1, store fp32 pairs
    const int rowc = mbase + (lane >> 2);
    const int col0 = wn * 64 + (lane & 3) * 2;
#pragma unroll
    for (int nf = 0; nf < 8; nf++) {
        int c = col0 + nf * 8;
        float b0 = __ldg(bias + c), b1 = __ldg(bias + c + 1);
        float v0 = acc[nf][0] + b0, v1 = acc[nf][1] + b1;
        float v2 = acc[nf][2] + b0, v3 = acc[nf][3] + b1;
        if (ACT) { v0 = featmap(v0); v1 = featmap(v1); v2 = featmap(v2); v3 = featmap(v3); }
        *(float2*)(dst + rowc * 132 + c) = make_float2(v0, v1);
        *(float2*)(dst + (rowc + 8) * 132 + c) = make_float2(v2, v3);
    }
}

// ---------------------------------------------------------------------------
// prep: W[k][o] fp32 -> fragment-ordered bf16 hi/lo uint4 images
// ---------------------------------------------------------------------------
__global__ void kPrep(const float* __restrict__ Wq, const float* __restrict__ Wk,
                      const float* __restrict__ Wv) {
    int gid = blockIdx.x * 256 + threadIdx.x;
    if (gid >= 20480) return;
    const float* W;
    uint4* img;
    int rel;
    if (gid < 8192)       { W = Wk; img = g_wk; rel = gid; }
    else if (gid < 16384) { W = Wq; img = g_wq; rel = gid - 8192; }
    else                  { W = Wv; img = g_wv; rel = gid - 16384; }
    int lane = rel & 31, gnks = rel >> 5;          // gnks = ks*16 + gn
    int k0 = (gnks >> 4) * 16 + (lane & 3) * 2;
    int o  = ((gnks & 15) << 3) + (lane >> 2);
    float v0 = W[(long)k0 * 128 + o];
    float v1 = W[(long)(k0 + 1) * 128 + o];
    float v2 = W[(long)(k0 + 8) * 128 + o];
    float v3 = W[(long)(k0 + 9) * 128 + o];
    uint32_t h01 = pack_hi(v0, v1);
    uint32_t h89 = pack_hi(v2, v3);
    float r0 = v0 - __uint_as_float(h01 << 16);
    float r1 = v1 - __uint_as_float(h01 & 0xffff0000u);
    float r2 = v2 - __uint_as_float(h89 << 16);
    float r3 = v3 - __uint_as_float(h89 & 0xffff0000u);
    uint32_t l01 = pack_hi(r0, r1);
    uint32_t l89 = pack_hi(r2, r3);
    img[rel] = make_uint4(h01, h89, l01, l89);
}

// ---------------------------------------------------------------------------
// Kernel A: K/V GEMMs + KV & Ksum.  smem = 168,960 B, 320 threads
// ---------------------------------------------------------------------------
enum { A_XH = 0, A_XL = 42240, A_KK = 84480, A_VV = 126720 };
#define A_SMEM 168960

__global__ void __launch_bounds__(320, 1)
kA(const float* __restrict__ x, const float* __restrict__ gdc,
   const float* __restrict__ bk, const float* __restrict__ bv) {
    extern __shared__ char sm[];
    const int n = blockIdx.x, tid = threadIdx.x;
    const int wid = tid >> 5, lane = tid & 31;
    float* kk = (float*)(sm + A_KK);
    float* vv = (float*)(sm + A_VV);

    conv_tile<64>(x + (long)n * SEQ * HID, HID, SEQ, sm + A_XH, sm + A_XL, 0, tid, 320);
    conv_tile<64>(gdc + (long)n * SEQ * HID, HID, SEQ, sm + A_XH, sm + A_XL, 128, tid, 320);
    // zero pad rows 77..79 (hi & lo)
    for (int i = tid; i < 396; i += 320) {
        int r = 77 + i / 132, c2 = (i % 132) * 2;
        *(uint32_t*)(sm + A_XH + (r * 264 + c2) * 2) = 0;
        *(uint32_t*)(sm + A_XL + (r * 264 + c2) * 2) = 0;
    }
    __syncthreads();

    uint32_t xh = smem_u32(sm + A_XH), xl = smem_u32(sm + A_XL);
    gemm_mma<16, true>(xh, xl, g_wk, bk, kk, wid, lane);   // K = elu(.)+1
    gemm_mma<8, false>(xh, xl, g_wv, bv, vv, wid, lane);   // V (x part: ksteps 0..7)
    __syncthreads();

    // Ksum
    if (tid < HID) {
        float s = 0.f;
        for (int t = 0; t < SEQ; t++) s += kk[t * 132 + tid];
        g_Ksum[(long)n * HID + tid] = s;
    }
    // KV: threads 0..255, each owns 8 dv of one (h,d)
    if (tid < 256) {
        const int h = tid >> 5;
        const int d = lane >> 1, dv0 = (lane & 1) * 8;
        float a[8] = {0, 0, 0, 0, 0, 0, 0, 0};
        for (int t = 0; t < SEQ; t++) {
            float kval = kk[t * 132 + h * 16 + d];
            float4 va = *(const float4*)(vv + t * 132 + h * 16 + dv0);
            float4 vb = *(const float4*)(vv + t * 132 + h * 16 + dv0 + 4);
            a[0] = fmaf(kval, va.x, a[0]); a[1] = fmaf(kval, va.y, a[1]);
            a[2] = fmaf(kval, va.z, a[2]); a[3] = fmaf(kval, va.w, a[3]);
            a[4] = fmaf(kval, vb.x, a[4]); a[5] = fmaf(kval, vb.y, a[5]);
            a[6] = fmaf(kval, vb.z, a[6]); a[7] = fmaf(kval, vb.w, a[7]);
        }
        float* dst = g_KV + (long)n * 2048 + tid * 8;
        *(float4*)dst = make_float4(a[0], a[1], a[2], a[3]);
        *(float4*)(dst + 4) = make_float4(a[4], a[5], a[6], a[7]);
    }
}

// ---------------------------------------------------------------------------
// Kernel B: Q GEMM + Z + output.  smem = 139,008 B, 320 threads
// ---------------------------------------------------------------------------
enum { B_QH = 0, B_QL = 42240, B_QQ = 84480, B_KVS = 126720,
       B_KS = 134912, B_ZS = 135424, B_RED = 137984 };
#define B_SMEM 139008

__global__ void __launch_bounds__(320, 1)
kB(const float* __restrict__ query, const float* __restrict__ bq,
   float* __restrict__ out) {
    extern __shared__ char sm[];
    const int n = blockIdx.x, tid = threadIdx.x;
    const int wid = tid >> 5, lane = tid & 31;
    float* qq  = (float*)(sm + B_QQ);
    float* kvs = (float*)(sm + B_KVS);
    float* ks  = (float*)(sm + B_KS);
    float* Zs  = (float*)(sm + B_ZS);
    float* red = (float*)(sm + B_RED);

    const int b = n / 576, rem = n - b * 576;
    const float* qbase = query + ((long)b * NQ * 576 + rem) * 256;

    conv_tile<128>(qbase, 576L * 256, NQ, sm + B_QH, sm + B_QL, 0, tid, 320);
    {   // stage KV / Ksum
        const float4* s = (const float4*)(g_KV + (long)n * 2048);
        for (int u = tid; u < 512; u += 320) ((float4*)kvs)[u] = s[u];
        if (tid < 32)
            ((float4*)ks)[tid] = ((const float4*)(g_Ksum + (long)n * HID))[tid];
    }
    __syncthreads();

    uint32_t qh = smem_u32(sm + B_QH), ql = smem_u32(sm + B_QL);
    gemm_mma<16, true>(qh, ql, g_wq, bq, qq, wid, lane);   // Q = elu(.)+1
    __syncthreads();

    // Z[l][h]
    for (int e = tid; e < NQ * 8; e += 320) {
        int l = e >> 3, h = e & 7;
        float dot = 0.f;
#pragma unroll
        for (int d = 0; d < 16; d++)
            dot = fmaf(qq[l * 132 + h * 16 + d], ks[h * 16 + d], dot);
        Zs[e] = 1.0f / (dot + 1e-6f);
    }
    __syncthreads();

    // out[c] = mean_l Z[l,h] * sum_d Q[l,h,d]*KV[h,d,dv]
    if (tid < 256) {
        const int c = tid & 127, g = tid >> 7;
        const int h = c >> 4, dv = c & 15;
        float kvc[16];
#pragma unroll
        for (int d = 0; d < 16; d++) kvc[d] = kvs[h * 256 + d * 16 + dv];
        float acc = 0.f;
        for (int l = g * 40; l < g * 40 + 40; l++) {
            const float4* qp = (const float4*)(qq + l * 132 + h * 16);
            float4 q0 = qp[0], q1 = qp[1], q2 = qp[2], q3 = qp[3];
            float p0 = fmaf(q0.x, kvc[0],  fmaf(q0.y, kvc[1],  fmaf(q0.z, kvc[2],  q0.w * kvc[3])));
            float p1 = fmaf(q1.x, kvc[4],  fmaf(q1.y, kvc[5],  fmaf(q1.z, kvc[6],  q1.w * kvc[7])));
            float p2 = fmaf(q2.x, kvc[8],  fmaf(q2.y, kvc[9],  fmaf(q2.z, kvc[10], q2.w * kvc[11])));
            float p3 = fmaf(q3.x, kvc[12], fmaf(q3.y, kvc[13], fmaf(q3.z, kvc[14], q3.w * kvc[15])));
            acc = fmaf(Zs[l * 8 + h], (p0 + p1) + (p2 + p3), acc);
        }
        red[tid] = acc;
    }
    __syncthreads();
    if (tid < HID)
        out[(long)n * HID + tid] = (red[tid] + red[tid + HID]) * (1.0f / 80.0f);
}

// ---------------------------------------------------------------------------
extern "C" void kernel_launch(void* const* d_in, const int* in_sizes, int n_in,
                              void* d_out, int out_size) {
    const float* query = (const float*)d_in[0];
    const float* x     = (const float*)d_in[1];
    const float* gdc   = (const float*)d_in[2];
    const float* Wq    = (const float*)d_in[3];
    const float* bq    = (const float*)d_in[4];
    const float* Wk    = (const float*)d_in[5];
    const float* bk    = (const float*)d_in[6];
    const float* Wv    = (const float*)d_in[7];
    const float* bv    = (const float*)d_in[8];
    float* out = (float*)d_out;

    cudaFuncSetAttribute(kA, cudaFuncAttributeMaxDynamicSharedMemorySize, A_SMEM);
    cudaFuncSetAttribute(kB, cudaFuncAttributeMaxDynamicSharedMemorySize, B_SMEM);

    kPrep<<<80, 256>>>(Wq, Wk, Wv);
    kA<<<NTOK, 320, A_SMEM>>>(x, gdc, bk, bv);
    kB<<<NTOK, 320, B_SMEM>>>(query, bq, out);
}

// round 5
// speedup vs baseline: 1.4573x; 1.0257x over previous
#include <cuda_runtime.h>
#include <cuda_bf16.h>
#include <cstdint>

// ---------------------------------------------------------------------------
// Linear attention, fully fused per-token kernel, mma.sync bf16-split.
//   n=2304, S=77, N=80, C=256, hidden=128, 8 heads x 16
// Per CTA (one token n):
//   conv x|g -> A tiles ; K,V GEMMs (tensor) ; kk/vv overlay A tiles ;
//   KV/Ksum reductions (smem) ; conv q -> A tiles ; Q GEMM ; qq overlay ;
//   Z = 1/(Q.Ksum+eps) ; out = mean_l Z*(Q.KV)
// Split: A=Ahi+Alo, W=Whi+Wlo (bf16); D += Ahi*Whi + Ahi*Wlo + Alo*Whi.
// Overlay safety: each warp's epilogue writes only its own M rows, and a
// __syncthreads() separates all A-tile reads from the overlay writes.
// ---------------------------------------------------------------------------

#define NTOK 2304
#define SEQ  77
#define NQ   80
#define HID  128

// fragment-ordered weight images: [kstep][gn][lane] -> uint4(hi01,hi89,lo01,lo89)
__device__ uint4 g_wk[16 * 16 * 32];   // K=256
__device__ uint4 g_wq[16 * 16 * 32];   // K=256
__device__ uint4 g_wv[8 * 16 * 32];    // K=128

// ---- helpers --------------------------------------------------------------
__device__ __forceinline__ uint32_t smem_u32(const void* p) {
    uint32_t a;
    asm("{ .reg .u64 t; cvta.to.shared.u64 t, %1; cvt.u32.u64 %0, t; }"
        : "=r"(a) : "l"(p));
    return a;
}
__device__ __forceinline__ void mma16816(float* d, const uint32_t* a,
                                         uint32_t b0, uint32_t b1) {
    asm volatile(
        "mma.sync.aligned.m16n8k16.row.col.f32.bf16.bf16.f32 "
        "{%0,%1,%2,%3}, {%4,%5,%6,%7}, {%8,%9}, {%0,%1,%2,%3};"
        : "+f"(d[0]), "+f"(d[1]), "+f"(d[2]), "+f"(d[3])
        : "r"(a[0]), "r"(a[1]), "r"(a[2]), "r"(a[3]), "r"(b0), "r"(b1));
}
__device__ __forceinline__ void ldsm4(uint32_t* r, uint32_t addr) {
    asm volatile("ldmatrix.sync.aligned.m8n8.x4.shared.b16 {%0,%1,%2,%3}, [%4];"
                 : "=r"(r[0]), "=r"(r[1]), "=r"(r[2]), "=r"(r[3]) : "r"(addr));
}
__device__ __forceinline__ uint32_t pack_hi(float v0, float v1) {
    uint32_t w;
    asm("cvt.rn.bf16x2.f32 %0, %1, %2;" : "=r"(w) : "f"(v1), "f"(v0));
    return w;  // lower half = v0
}
__device__ __forceinline__ float featmap(float x) {
    return x > 0.f ? x + 1.f : __expf(x);
}

// fp32 rows -> bf16 hi/lo into smem A-tiles, row stride 264 elements (528 B)
template <int PAIRS>
__device__ __forceinline__ void conv_tile(const float* __restrict__ src,
                                          long rstride, int rows, char* hi_base,
                                          char* lo_base, int colbase, int tid) {
    for (int idx = tid; idx < rows * PAIRS; idx += 320) {
        int r = idx / PAIRS, j = idx % PAIRS;
        float2 v = *(const float2*)(src + (long)r * rstride + 2 * j);
        uint32_t hw = pack_hi(v.x, v.y);
        float r0 = v.x - __uint_as_float(hw << 16);
        float r1 = v.y - __uint_as_float(hw & 0xffff0000u);
        uint32_t lw = pack_hi(r0, r1);
        int off = (r * 264 + colbase + 2 * j) * 2;
        *(uint32_t*)(hi_base + off) = hw;
        *(uint32_t*)(lo_base + off) = lw;
    }
}

// MMA accumulation only (no epilogue): warp (wm = wid>>1, wn = wid&1),
// depth-2 circular weight prefetch.
template <int KSTEPS>
__device__ __forceinline__ void gemm_acc(uint32_t ahi, uint32_t alo,
                                         const uint4* __restrict__ wimg,
                                         float acc[8][4], int wid, int lane) {
    const int wm = wid >> 1, wn = wid & 1;
    const int mbase = wm * 16;
    const int row_a = mbase + (lane & 7) + ((lane >> 3) & 1) * 8;
    const int kbyte = (lane >> 4) * 16;
    const uint32_t a_hi = ahi + row_a * 528 + kbyte;
    const uint32_t a_lo = alo + row_a * 528 + kbyte;

    uint4 wb0[8], wb1[8];
#pragma unroll
    for (int nf = 0; nf < 8; nf++) {
        wb0[nf] = wimg[(0 * 16 + wn * 8 + nf) * 32 + lane];
        if (KSTEPS > 1) wb1[nf] = wimg[(1 * 16 + wn * 8 + nf) * 32 + lane];
    }
    for (int ks = 0; ks < KSTEPS; ks++) {
        uint4 wbn[8];
        if (ks + 2 < KSTEPS) {
#pragma unroll
            for (int nf = 0; nf < 8; nf++)
                wbn[nf] = wimg[((ks + 2) * 16 + wn * 8 + nf) * 32 + lane];
        }
        uint32_t ah[4], al[4];
        ldsm4(ah, a_hi + ks * 32);
        ldsm4(al, a_lo + ks * 32);
#pragma unroll
        for (int nf = 0; nf < 8; nf++) {
            mma16816(acc[nf], ah, wb0[nf].x, wb0[nf].y);   // hi*Whi
            mma16816(acc[nf], ah, wb0[nf].z, wb0[nf].w);   // hi*Wlo
            mma16816(acc[nf], al, wb0[nf].x, wb0[nf].y);   // lo*Whi
        }
#pragma unroll
        for (int nf = 0; nf < 8; nf++) {
            wb0[nf] = wb1[nf];
            if (ks + 2 < KSTEPS) wb1[nf] = wbn[nf];
        }
    }
}

// epilogue: bias (+optional elu+1), store fp32 to dst (row stride 132 fp32)
template <bool ACT>
__device__ __forceinline__ void epi(const float acc[8][4],
                                    const float* __restrict__ bias, float* dst,
                                    int wid, int lane) {
    const int wm = wid >> 1, wn = wid & 1;
    const int rowc = wm * 16 + (lane >> 2);
    const int col0 = wn * 64 + (lane & 3) * 2;
#pragma unroll
    for (int nf = 0; nf < 8; nf++) {
        int c = col0 + nf * 8;
        float b0 = __ldg(bias + c), b1 = __ldg(bias + c + 1);
        float v0 = acc[nf][0] + b0, v1 = acc[nf][1] + b1;
        float v2 = acc[nf][2] + b0, v3 = acc[nf][3] + b1;
        if (ACT) { v0 = featmap(v0); v1 = featmap(v1); v2 = featmap(v2); v3 = featmap(v3); }
        *(float2*)(dst + rowc * 132 + c) = make_float2(v0, v1);
        *(float2*)(dst + (rowc + 8) * 132 + c) = make_float2(v2, v3);
    }
}

// ---------------------------------------------------------------------------
// prep: W[k][o] fp32 -> fragment-ordered bf16 hi/lo uint4 images
// ---------------------------------------------------------------------------
__global__ void kPrep(const float* __restrict__ Wq, const float* __restrict__ Wk,
                      const float* __restrict__ Wv) {
    int gid = blockIdx.x * 256 + threadIdx.x;
    if (gid >= 20480) return;
    const float* W;
    uint4* img;
    int rel;
    if (gid < 8192)       { W = Wk; img = g_wk; rel = gid; }
    else if (gid < 16384) { W = Wq; img = g_wq; rel = gid - 8192; }
    else                  { W = Wv; img = g_wv; rel = gid - 16384; }
    int lane = rel & 31, gnks = rel >> 5;          // gnks = ks*16 + gn
    int k0 = (gnks >> 4) * 16 + (lane & 3) * 2;
    int o  = ((gnks & 15) << 3) + (lane >> 2);
    float v0 = W[(long)k0 * 128 + o];
    float v1 = W[(long)(k0 + 1) * 128 + o];
    float v2 = W[(long)(k0 + 8) * 128 + o];
    float v3 = W[(long)(k0 + 9) * 128 + o];
    uint32_t h01 = pack_hi(v0, v1);
    uint32_t h89 = pack_hi(v2, v3);
    float r0 = v0 - __uint_as_float(h01 << 16);
    float r1 = v1 - __uint_as_float(h01 & 0xffff0000u);
    float r2 = v2 - __uint_as_float(h89 << 16);
    float r3 = v3 - __uint_as_float(h89 & 0xffff0000u);
    uint32_t l01 = pack_hi(r0, r1);
    uint32_t l89 = pack_hi(r2, r3);
    img[rel] = make_uint4(h01, h89, l01, l89);
}

// ---------------------------------------------------------------------------
// Fused kernel: everything for one token.  smem = 97,024 B, 320 threads
// ---------------------------------------------------------------------------
enum { M_R1 = 0, M_R2 = 42240, M_KVS = 84480, M_KS = 92672,
       M_ZS = 93184, M_RED = 95744 };
#define M_SMEM 97024

__global__ void __launch_bounds__(320, 1)
kMain(const float* __restrict__ query, const float* __restrict__ x,
      const float* __restrict__ gdc, const float* __restrict__ bq,
      const float* __restrict__ bk, const float* __restrict__ bv,
      float* __restrict__ out) {
    extern __shared__ char sm[];
    const int n = blockIdx.x, tid = threadIdx.x;
    const int wid = tid >> 5, lane = tid & 31;
    char* R1 = sm + M_R1;
    char* R2 = sm + M_R2;
    float* kvs = (float*)(sm + M_KVS);
    float* ks  = (float*)(sm + M_KS);
    float* Zs  = (float*)(sm + M_ZS);
    float* red = (float*)(sm + M_RED);
    float* kk  = (float*)R1;   // overlays after epilogues
    float* vv  = (float*)R2;
    float* qq  = (float*)R1;

    // ---- phase 1: convert x|g into A tiles --------------------------------
    conv_tile<64>(x + (long)n * SEQ * HID, HID, SEQ, R1, R2, 0, tid);
    conv_tile<64>(gdc + (long)n * SEQ * HID, HID, SEQ, R1, R2, 128, tid);
    for (int i = tid; i < 396; i += 320) {              // zero rows 77..79
        int r = 77 + i / 132, c2 = (i % 132) * 2;
        *(uint32_t*)(R1 + (r * 264 + c2) * 2) = 0;
        *(uint32_t*)(R2 + (r * 264 + c2) * 2) = 0;
    }
    __syncthreads();

    // ---- phase 2: K and V GEMMs (acc in regs, epilogues after sync) -------
    const uint32_t ahi = smem_u32(R1), alo = smem_u32(R2);
    float accK[8][4], accV[8][4];
#pragma unroll
    for (int i = 0; i < 8; i++)
#pragma unroll
        for (int p = 0; p < 4; p++) { accK[i][p] = 0.f; accV[i][p] = 0.f; }
    gemm_acc<16>(ahi, alo, g_wk, accK, wid, lane);
    gemm_acc<8>(ahi, alo, g_wv, accV, wid, lane);
    __syncthreads();                                    // all A reads done
    epi<true>(accK, bk, kk, wid, lane);                 // K = elu(.)+1 -> R1
    epi<false>(accV, bv, vv, wid, lane);                // V -> R2
    __syncthreads();

    // ---- phase 3: Ksum + KV reductions ------------------------------------
    if (tid < HID) {
        float s = 0.f;
        for (int t = 0; t < SEQ; t++) s += kk[t * 132 + tid];
        ks[tid] = s;
    }
    if (tid < 256) {
        const int h = tid >> 5, l5 = tid & 31;
        const int d = l5 >> 1, dv0 = (l5 & 1) * 8;
        float a[8] = {0, 0, 0, 0, 0, 0, 0, 0};
        for (int t = 0; t < SEQ; t++) {
            float kval = kk[t * 132 + h * 16 + d];
            float4 va = *(const float4*)(vv + t * 132 + h * 16 + dv0);
            float4 vb = *(const float4*)(vv + t * 132 + h * 16 + dv0 + 4);
            a[0] = fmaf(kval, va.x, a[0]); a[1] = fmaf(kval, va.y, a[1]);
            a[2] = fmaf(kval, va.z, a[2]); a[3] = fmaf(kval, va.w, a[3]);
            a[4] = fmaf(kval, vb.x, a[4]); a[5] = fmaf(kval, vb.y, a[5]);
            a[6] = fmaf(kval, vb.z, a[6]); a[7] = fmaf(kval, vb.w, a[7]);
        }
        float* dst = kvs + tid * 8;
        *(float4*)dst = make_float4(a[0], a[1], a[2], a[3]);
        *(float4*)(dst + 4) = make_float4(a[4], a[5], a[6], a[7]);
    }
    __syncthreads();                                    // kk/vv dead after this

    // ---- phase 4: convert q, Q GEMM ---------------------------------------
    const int b = n / 576, rem = n - b * 576;
    const float* qbase = query + ((long)b * NQ * 576 + rem) * 256;
    conv_tile<128>(qbase, 576L * 256, NQ, R1, R2, 0, tid);
    __syncthreads();

    float accQ[8][4];
#pragma unroll
    for (int i = 0; i < 8; i++)
#pragma unroll
        for (int p = 0; p < 4; p++) accQ[i][p] = 0.f;
    gemm_acc<16>(ahi, alo, g_wq, accQ, wid, lane);
    __syncthreads();
    epi<true>(accQ, bq, qq, wid, lane);                 // Q = elu(.)+1 -> R1
    __syncthreads();

    // ---- phase 5: Z -------------------------------------------------------
    for (int e = tid; e < NQ * 8; e += 320) {
        int l = e >> 3, h = e & 7;
        float dot = 0.f;
#pragma unroll
        for (int d = 0; d < 16; d++)
            dot = fmaf(qq[l * 132 + h * 16 + d], ks[h * 16 + d], dot);
        Zs[e] = 1.0f / (dot + 1e-6f);
    }
    __syncthreads();

    // ---- phase 6: out[c] = mean_l Z[l,h] * sum_d Q[l,h,d]*KV[h,d,dv] ------
    if (tid < 256) {
        const int c = tid & 127, g = tid >> 7;
        const int h = c >> 4, dv = c & 15;
        float kvc[16];
#pragma unroll
        for (int d = 0; d < 16; d++) kvc[d] = kvs[h * 256 + d * 16 + dv];
        float acc = 0.f;
        for (int l = g * 40; l < g * 40 + 40; l++) {
            const float4* qp = (const float4*)(qq + l * 132 + h * 16);
            float4 q0 = qp[0], q1 = qp[1], q2 = qp[2], q3 = qp[3];
            float p0 = fmaf(q0.x, kvc[0],  fmaf(q0.y, kvc[1],  fmaf(q0.z, kvc[2],  q0.w * kvc[3])));
            float p1 = fmaf(q1.x, kvc[4],  fmaf(q1.y, kvc[5],  fmaf(q1.z, kvc[6],  q1.w * kvc[7])));
            float p2 = fmaf(q2.x, kvc[8],  fmaf(q2.y, kvc[9],  fmaf(q2.z, kvc[10], q2.w * kvc[11])));
            float p3 = fmaf(q3.x, kvc[12], fmaf(q3.y, kvc[13], fmaf(q3.z, kvc[14], q3.w * kvc[15])));
            acc = fmaf(Zs[l * 8 + h], (p0 + p1) + (p2 + p3), acc);
        }
        red[tid] = acc;
    }
    __syncthreads();
    if (tid < HID)
        out[(long)n * HID + tid] = (red[tid] + red[tid + HID]) * (1.0f / 80.0f);
}

// ---------------------------------------------------------------------------
extern "C" void kernel_launch(void* const* d_in, const int* in_sizes, int n_in,
                              void* d_out, int out_size) {
    const float* query = (const float*)d_in[0];
    const float* x     = (const float*)d_in[1];
    const float* gdc   = (const float*)d_in[2];
    const float* Wq    = (const float*)d_in[3];
    const float* bq    = (const float*)d_in[4];
    const float* Wk    = (const float*)d_in[5];
    const float* bk    = (const float*)d_in[6];
    const float* Wv    = (const float*)d_in[7];
    const float* bv    = (const float*)d_in[8];
    float* out = (float*)d_out;

    cudaFuncSetAttribute(kMain, cudaFuncAttributeMaxDynamicSharedMemorySize, M_SMEM);

    kPrep<<<80, 256>>>(Wq, Wk, Wv);
    kMain<<<NTOK, 320, M_SMEM>>>(query, x, gdc, bq, bk, bv, out);
}

// round 8
// speedup vs baseline: 2.5893x; 1.7768x over previous
#include <cuda_runtime.h>
#include <cuda_bf16.h>
#include <cstdint>

// ---------------------------------------------------------------------------
// Linear attention, fused per-token kernel, mma.sync bf16-split, 2 CTAs/SM.
//   n=2304, S=77, N=80, C=256, hidden=128, 8 heads x 16
// Serialized K->V GEMMs with ONE live accumulator set; fp32 K/V staging via
// disjoint-region overlay of the A tiles:
//   K epilogue -> bytes 256..527 of each row (g-half, dead after K GEMM)
//   V epilogue -> bytes 0..255  of each row (x-half, dead after V GEMM)
// All staging fp32 => no bf16 KV precision loss (R7 lesson).
// Split GEMM: A=Ahi+Alo, W=Whi+Wlo (bf16); D += Ahi*Whi + Ahi*Wlo + Alo*Whi.
// ---------------------------------------------------------------------------

#define NTOK 2304
#define SEQ  77
#define NQ   80
#define HID  128

// fragment-ordered weight images: [kstep][gn][lane] -> uint4(hi01,hi89,lo01,lo89)
__device__ uint4 g_wk[16 * 16 * 32];   // K=256
__device__ uint4 g_wq[16 * 16 * 32];   // K=256
__device__ uint4 g_wv[8 * 16 * 32];    // K=128

// ---- helpers --------------------------------------------------------------
__device__ __forceinline__ uint32_t smem_u32(const void* p) {
    uint32_t a;
    asm("{ .reg .u64 t; cvta.to.shared.u64 t, %1; cvt.u32.u64 %0, t; }"
        : "=r"(a) : "l"(p));
    return a;
}
__device__ __forceinline__ void mma16816(float* d, const uint32_t* a,
                                         uint32_t b0, uint32_t b1) {
    asm volatile(
        "mma.sync.aligned.m16n8k16.row.col.f32.bf16.bf16.f32 "
        "{%0,%1,%2,%3}, {%4,%5,%6,%7}, {%8,%9}, {%0,%1,%2,%3};"
        : "+f"(d[0]), "+f"(d[1]), "+f"(d[2]), "+f"(d[3])
        : "r"(a[0]), "r"(a[1]), "r"(a[2]), "r"(a[3]), "r"(b0), "r"(b1));
}
__device__ __forceinline__ void ldsm4(uint32_t* r, uint32_t addr) {
    asm volatile("ldmatrix.sync.aligned.m8n8.x4.shared.b16 {%0,%1,%2,%3}, [%4];"
                 : "=r"(r[0]), "=r"(r[1]), "=r"(r[2]), "=r"(r[3]) : "r"(addr));
}
__device__ __forceinline__ uint32_t pack_hi(float v0, float v1) {
    uint32_t w;
    asm("cvt.rn.bf16x2.f32 %0, %1, %2;" : "=r"(w) : "f"(v1), "f"(v0));
    return w;  // lower half = v0
}
__device__ __forceinline__ float featmap(float x) {
    return x > 0.f ? x + 1.f : __expf(x);
}

// fp32 rows -> bf16 hi/lo into smem A-tiles, row stride 264 elements (528 B)
template <int PAIRS>
__device__ __forceinline__ void conv_tile(const float* __restrict__ src,
                                          long rstride, int rows, char* hi_base,
                                          char* lo_base, int colbase, int tid) {
    for (int idx = tid; idx < rows * PAIRS; idx += 320) {
        int r = idx / PAIRS, j = idx % PAIRS;
        float2 v = *(const float2*)(src + (long)r * rstride + 2 * j);
        uint32_t hw = pack_hi(v.x, v.y);
        float r0 = v.x - __uint_as_float(hw << 16);
        float r1 = v.y - __uint_as_float(hw & 0xffff0000u);
        uint32_t lw = pack_hi(r0, r1);
        int off = (r * 264 + colbase + 2 * j) * 2;
        *(uint32_t*)(hi_base + off) = hw;
        *(uint32_t*)(lo_base + off) = lw;
    }
}

// MMA accumulation: warp (wm = wid>>1, wn = wid&1), depth-1 interleaved
// weight prefetch (low register pressure; TLP hides L2 with 20 warps/SM).
template <int KSTEPS>
__device__ __forceinline__ void gemm_acc(uint32_t ahi, uint32_t alo,
                                         const uint4* __restrict__ wimg,
                                         float acc[8][4], int wid, int lane) {
    const int wm = wid >> 1, wn = wid & 1;
    const int row_a = wm * 16 + (lane & 7) + ((lane >> 3) & 1) * 8;
    const uint32_t a_hi = ahi + row_a * 528 + (lane >> 4) * 16;
    const uint32_t a_lo = alo + row_a * 528 + (lane >> 4) * 16;
    const uint4* wbase = wimg + (wn * 8) * 32 + lane;

    uint4 wb[8];
#pragma unroll
    for (int nf = 0; nf < 8; nf++) wb[nf] = wbase[nf * 32];
    for (int ks = 0; ks < KSTEPS; ks++) {
        uint32_t ah[4], al[4];
        ldsm4(ah, a_hi + ks * 32);
        ldsm4(al, a_lo + ks * 32);
        const int ksn = (ks + 1 < KSTEPS) ? ks + 1 : ks;
#pragma unroll
        for (int nf = 0; nf < 8; nf++) {
            uint4 nxt = wbase[(ksn * 16 + nf) * 32];
            mma16816(acc[nf], ah, wb[nf].x, wb[nf].y);   // hi*Whi
            mma16816(acc[nf], ah, wb[nf].z, wb[nf].w);   // hi*Wlo
            mma16816(acc[nf], al, wb[nf].x, wb[nf].y);   // lo*Whi
            wb[nf] = nxt;
        }
    }
}

// split-plane fp32 epilogue: wn==0 warps -> dstA[row*132 + (c&63)],
// wn==1 warps -> dstB[row*132 + (c&63)].  (+bias, opt elu+1)
template <bool ACT>
__device__ __forceinline__ void epi_split(const float acc[8][4],
                                          const float* __restrict__ bias,
                                          float* dstA, float* dstB,
                                          int wid, int lane) {
    const int rowc = (wid >> 1) * 16 + (lane >> 2);
    const int col0 = (wid & 1) * 64 + (lane & 3) * 2;
    float* base = (wid & 1) ? dstB : dstA;
#pragma unroll
    for (int nf = 0; nf < 8; nf++) {
        int c = col0 + nf * 8;
        int c64 = c & 63;
        float b0 = __ldg(bias + c), b1 = __ldg(bias + c + 1);
        float v0 = acc[nf][0] + b0, v1 = acc[nf][1] + b1;
        float v2 = acc[nf][2] + b0, v3 = acc[nf][3] + b1;
        if (ACT) { v0 = featmap(v0); v1 = featmap(v1); v2 = featmap(v2); v3 = featmap(v3); }
        *(float2*)(base + rowc * 132 + c64) = make_float2(v0, v1);
        *(float2*)(base + (rowc + 8) * 132 + c64) = make_float2(v2, v3);
    }
}

// full-width fp32 epilogue (Q): dst row stride 132 fp32, cols 0..127
template <bool ACT>
__device__ __forceinline__ void epi_f32(const float acc[8][4],
                                        const float* __restrict__ bias,
                                        float* dst, int wid, int lane) {
    const int rowc = (wid >> 1) * 16 + (lane >> 2);
    const int col0 = (wid & 1) * 64 + (lane & 3) * 2;
#pragma unroll
    for (int nf = 0; nf < 8; nf++) {
        int c = col0 + nf * 8;
        float b0 = __ldg(bias + c), b1 = __ldg(bias + c + 1);
        float v0 = acc[nf][0] + b0, v1 = acc[nf][1] + b1;
        float v2 = acc[nf][2] + b0, v3 = acc[nf][3] + b1;
        if (ACT) { v0 = featmap(v0); v1 = featmap(v1); v2 = featmap(v2); v3 = featmap(v3); }
        *(float2*)(dst + rowc * 132 + c) = make_float2(v0, v1);
        *(float2*)(dst + (rowc + 8) * 132 + c) = make_float2(v2, v3);
    }
}

// ---------------------------------------------------------------------------
// prep: W[k][o] fp32 -> fragment-ordered bf16 hi/lo uint4 images
// ---------------------------------------------------------------------------
__global__ void kPrep(const float* __restrict__ Wq, const float* __restrict__ Wk,
                      const float* __restrict__ Wv) {
    int gid = blockIdx.x * 256 + threadIdx.x;
    if (gid >= 20480) return;
    const float* W;
    uint4* img;
    int rel;
    if (gid < 8192)       { W = Wk; img = g_wk; rel = gid; }
    else if (gid < 16384) { W = Wq; img = g_wq; rel = gid - 8192; }
    else                  { W = Wv; img = g_wv; rel = gid - 16384; }
    int lane = rel & 31, gnks = rel >> 5;          // gnks = ks*16 + gn
    int k0 = (gnks >> 4) * 16 + (lane & 3) * 2;
    int o  = ((gnks & 15) << 3) + (lane >> 2);
    float v0 = W[(long)k0 * 128 + o];
    float v1 = W[(long)(k0 + 1) * 128 + o];
    float v2 = W[(long)(k0 + 8) * 128 + o];
    float v3 = W[(long)(k0 + 9) * 128 + o];
    uint32_t h01 = pack_hi(v0, v1);
    uint32_t h89 = pack_hi(v2, v3);
    float r0 = v0 - __uint_as_float(h01 << 16);
    float r1 = v1 - __uint_as_float(h01 & 0xffff0000u);
    float r2 = v2 - __uint_as_float(h89 << 16);
    float r3 = v3 - __uint_as_float(h89 & 0xffff0000u);
    uint32_t l01 = pack_hi(r0, r1);
    uint32_t l89 = pack_hi(r2, r3);
    img[rel] = make_uint4(h01, h89, l01, l89);
}

// ---------------------------------------------------------------------------
// Fused kernel.  smem = 97,024 B, 320 threads, 2 CTAs/SM.
// Layout: R1 42,240 | R2 42,240 | kvs 8,192 | ks 512 | Zs 2,560 | red 1,280
// ---------------------------------------------------------------------------
enum { M_R1 = 0, M_R2 = 42240, M_KVS = 84480, M_KS = 92672,
       M_ZS = 93184, M_RED = 95744 };
#define M_SMEM 97024

__global__ void __launch_bounds__(320, 2)
kMain(const float* __restrict__ query, const float* __restrict__ x,
      const float* __restrict__ gdc, const float* __restrict__ bq,
      const float* __restrict__ bk, const float* __restrict__ bv,
      float* __restrict__ out) {
    extern __shared__ char sm[];
    const int n = blockIdx.x, tid = threadIdx.x;
    const int wid = tid >> 5, lane = tid & 31;
    char* R1 = sm + M_R1;
    char* R2 = sm + M_R2;
    float* R1f = (float*)R1;
    float* R2f = (float*)R2;
    float* kvs = (float*)(sm + M_KVS);
    float* ks  = (float*)(sm + M_KS);
    float* Zs  = (float*)(sm + M_ZS);
    float* red = (float*)(sm + M_RED);
    float* qq  = R1f;          // fp32 overlay after Q epilogue

    // ---- phase 1: convert x|g into A tiles --------------------------------
    conv_tile<64>(x + (long)n * SEQ * HID, HID, SEQ, R1, R2, 0, tid);
    conv_tile<64>(gdc + (long)n * SEQ * HID, HID, SEQ, R1, R2, 128, tid);
    for (int i = tid; i < 396; i += 320) {              // zero rows 77..79
        int r = 77 + i / 132, c2 = (i % 132) * 2;
        *(uint32_t*)(R1 + (r * 264 + c2) * 2) = 0;
        *(uint32_t*)(R2 + (r * 264 + c2) * 2) = 0;
    }
    __syncthreads();

    const uint32_t ahi = smem_u32(R1), alo = smem_u32(R2);

    // ---- phase 2a: K GEMM -> epilogue into dead g-half (bytes 256..527) ---
    {
        float acc[8][4];
#pragma unroll
        for (int i = 0; i < 8; i++)
#pragma unroll
            for (int p = 0; p < 4; p++) acc[i][p] = 0.f;
        gemm_acc<16>(ahi, alo, g_wk, acc, wid, lane);
        __syncthreads();                    // all K-GEMM A reads done
        // K cols 0..63 -> R1f[r*132+64+c64], cols 64..127 -> R2f[r*132+64+c64]
        epi_split<true>(acc, bk, R1f + 64, R2f + 64, wid, lane);
    }
    // no sync needed: V GEMM reads bytes 0..255 only (disjoint from K writes)

    // ---- phase 2b: V GEMM (reuses acc regs) -> epilogue into x-half -------
    {
        float acc[8][4];
#pragma unroll
        for (int i = 0; i < 8; i++)
#pragma unroll
            for (int p = 0; p < 4; p++) acc[i][p] = 0.f;
        gemm_acc<8>(ahi, alo, g_wv, acc, wid, lane);
        __syncthreads();                    // all V-GEMM A reads done
        // V cols 0..63 -> R1f[r*132+c64], cols 64..127 -> R2f[r*132+c64]
        epi_split<false>(acc, bv, R1f, R2f, wid, lane);
    }
    __syncthreads();

    // staged layouts (all fp32):
    //   K(t,c) = c<64 ? R1f[t*132+64+c] : R2f[t*132+c]
    //   V(t,c) = c<64 ? R1f[t*132+c]    : R2f[t*132+(c-64)]

    // ---- phase 3: Ksum + KV -----------------------------------------------
    if (tid < HID) {
        const float* kp = (tid < 64) ? (R1f + 64 + tid) : (R2f + tid);
        float s = 0.f;
        for (int t = 0; t < SEQ; t++) s += kp[t * 132];
        ks[tid] = s;
    }
    if (tid < 256) {
        const int h = tid >> 5, l5 = tid & 31;
        const int d = l5 >> 1, dv0 = (l5 & 1) * 8;
        const int ck = h * 16 + d;                         // K column
        const float* kp = (ck < 64) ? (R1f + 64 + ck) : (R2f + ck);
        const int cv = h * 16 + dv0;                       // V column (8-block)
        const float* vp = (cv < 64) ? (R1f + cv) : (R2f + (cv - 64));
        float a[8] = {0, 0, 0, 0, 0, 0, 0, 0};
        for (int t = 0; t < SEQ; t++) {
            float kval = kp[t * 132];
            float4 va = *(const float4*)(vp + t * 132);
            float4 vb = *(const float4*)(vp + t * 132 + 4);
            a[0] = fmaf(kval, va.x, a[0]); a[1] = fmaf(kval, va.y, a[1]);
            a[2] = fmaf(kval, va.z, a[2]); a[3] = fmaf(kval, va.w, a[3]);
            a[4] = fmaf(kval, vb.x, a[4]); a[5] = fmaf(kval, vb.y, a[5]);
            a[6] = fmaf(kval, vb.z, a[6]); a[7] = fmaf(kval, vb.w, a[7]);
        }
        float* dst = kvs + tid * 8;
        *(float4*)dst = make_float4(a[0], a[1], a[2], a[3]);
        *(float4*)(dst + 4) = make_float4(a[4], a[5], a[6], a[7]);
    }
    __syncthreads();                                    // K/V staging dead

    // ---- phase 4: convert q, Q GEMM ---------------------------------------
    const int b = n / 576, rem = n - b * 576;
    const float* qbase = query + ((long)b * NQ * 576 + rem) * 256;
    conv_tile<128>(qbase, 576L * 256, NQ, R1, R2, 0, tid);
    __syncthreads();
    {
        float acc[8][4];
#pragma unroll
        for (int i = 0; i < 8; i++)
#pragma unroll
            for (int p = 0; p < 4; p++) acc[i][p] = 0.f;
        gemm_acc<16>(ahi, alo, g_wq, acc, wid, lane);
        __syncthreads();
        epi_f32<true>(acc, bq, qq, wid, lane);          // Q = elu(.)+1 -> R1
    }
    __syncthreads();

    // ---- phase 5: Z -------------------------------------------------------
    for (int e = tid; e < NQ * 8; e += 320) {
        int l = e >> 3, h = e & 7;
        float dot = 0.f;
#pragma unroll
        for (int d = 0; d < 16; d++)
            dot = fmaf(qq[l * 132 + h * 16 + d], ks[h * 16 + d], dot);
        Zs[e] = 1.0f / (dot + 1e-6f);
    }
    __syncthreads();

    // ---- phase 6: out[c] = mean_l Z[l,h] * sum_d Q[l,h,d]*KV[h,d,dv] ------
    if (tid < 256) {
        const int c = tid & 127, g = tid >> 7;
        const int h = c >> 4, dv = c & 15;
        float kvc[16];
#pragma unroll
        for (int d = 0; d < 16; d++) kvc[d] = kvs[h * 256 + d * 16 + dv];
        float acc = 0.f;
        for (int l = g * 40; l < g * 40 + 40; l++) {
            const float4* qp = (const float4*)(qq + l * 132 + h * 16);
            float4 q0 = qp[0], q1 = qp[1], q2 = qp[2], q3 = qp[3];
            float p0 = fmaf(q0.x, kvc[0],  fmaf(q0.y, kvc[1],  fmaf(q0.z, kvc[2],  q0.w * kvc[3])));
            float p1 = fmaf(q1.x, kvc[4],  fmaf(q1.y, kvc[5],  fmaf(q1.z, kvc[6],  q1.w * kvc[7])));
            float p2 = fmaf(q2.x, kvc[8],  fmaf(q2.y, kvc[9],  fmaf(q2.z, kvc[10], q2.w * kvc[11])));
            float p3 = fmaf(q3.x, kvc[12], fmaf(q3.y, kvc[13], fmaf(q3.z, kvc[14], q3.w * kvc[15])));
            acc = fmaf(Zs[l * 8 + h], (p0 + p1) + (p2 + p3), acc);
        }
        red[tid] = acc;
    }
    __syncthreads();
    if (tid < HID)
        out[(long)n * HID + tid] = (red[tid] + red[tid + HID]) * (1.0f / 80.0f);
}

// ---------------------------------------------------------------------------
extern "C" void kernel_launch(void* const* d_in, const int* in_sizes, int n_in,
                              void* d_out, int out_size) {
    const float* query = (const float*)d_in[0];
    const float* x     = (const float*)d_in[1];
    const float* gdc   = (const float*)d_in[2];
    const float* Wq    = (const float*)d_in[3];
    const float* bq    = (const float*)d_in[4];
    const float* Wk    = (const float*)d_in[5];
    const float* bk    = (const float*)d_in[6];
    const float* Wv    = (const float*)d_in[7];
    const float* bv    = (const float*)d_in[8];
    float* out = (float*)d_out;

    cudaFuncSetAttribute(kMain, cudaFuncAttributeMaxDynamicSharedMemorySize, M_SMEM);

    kPrep<<<80, 256>>>(Wq, Wk, Wv);
    kMain<<<NTOK, 320, M_SMEM>>>(query, x, gdc, bq, bk, bv, out);
}